// round 15
// baseline (speedup 1.0000x reference)
#include <cuda_runtime.h>

// FIR: out[b,t,c] = sum_{i=0..15} w[i,c] * x[b, t-15+i, c]   (causal, zero-padded)
// x: [B=64, T=2048, C=32] fp32, w: [16, 32] fp32, out: [B, T, C] fp32.
//
// Round 15: 128-bit everything to halve LSU dispatch cost (the invariant that
// pinned R2-R14 at ~9us). Thread = one channel QUAD x 8 timesteps. Outer loop
// over taps with an 8-deep float4 register ring (tap is single-live -> no
// 64-reg tap array). 47 memory instructions per 32 outputs (1.47/output,
// -50% vs R9), all LDG.128/STG.128. Math stays fma.rn.f32x2 (2 per quad-tap).

#define B_SZ 64
#define T_SZ 2048
#define C_SZ 32
#define F_SZ 16
#define GRP  8
#define NQ   (C_SZ / 4)          // 8 quads per timestep row
#define THREADS 128

typedef unsigned long long u64;
typedef ulonglong2 q4;           // 4 packed floats = 2 x f32x2

__device__ __forceinline__ u64 fma2(u64 a, u64 b, u64 c) {
    u64 d;
    asm("fma.rn.f32x2 %0, %1, %2, %3;" : "=l"(d) : "l"(a), "l"(b), "l"(c));
    return d;
}
__device__ __forceinline__ u64 mul2(u64 a, u64 b) {
    u64 d;
    asm("mul.rn.f32x2 %0, %1, %2;" : "=l"(d) : "l"(a), "l"(b));
    return d;
}

// One item: 8 timesteps x 4 channels for quad q. xq/oq point at (t0, quad) in
// q4 units (row stride NQ). wq points at (tap 0, quad). EDGE: window times
// t < 0 are zero padding (also blocks cross-batch reads).
//
// Value indexing: step i (tap), output u: needs x[t0 + (i+u) - 15]. m = i+u in
// [0,30]... here m in [0,22]; ring slot m&7. Prefill m=0..7; at step i>=1 load
// m = i+7.
template <bool EDGE>
__device__ __forceinline__ void fir_item(const q4* __restrict__ xq,
                                         q4* __restrict__ oq,
                                         const q4* __restrict__ wq,
                                         int t0) {
    u64 rl[GRP], rh[GRP];
#pragma unroll
    for (int m = 0; m < GRP; m++) {
        if (EDGE && (t0 + m - 15) < 0) {
            rl[m] = 0ULL; rh[m] = 0ULL;
        } else {
            const q4 v = xq[(m - 15) * NQ];
            rl[m] = v.x; rh[m] = v.y;
        }
    }

    u64 al[GRP], ah[GRP];
#pragma unroll
    for (int i = 0; i < F_SZ; i++) {
        if (i >= 1) {                         // slide ring: load m = i+7
            const int m = i + 7;
            const int s = m & (GRP - 1);
            if (EDGE && (t0 + m - 15) < 0) {
                rl[s] = 0ULL; rh[s] = 0ULL;
            } else {
                const q4 v = xq[(m - 15) * NQ];
                rl[s] = v.x; rh[s] = v.y;
            }
        }
        const q4 wv = wq[i * NQ];             // tap quad, 1 line (lane-dedup)
#pragma unroll
        for (int u = 0; u < GRP; u++) {
            const int s = (i + u) & (GRP - 1);
            if (i == 0) {
                al[u] = mul2(wv.x, rl[s]);
                ah[u] = mul2(wv.y, rh[s]);
            } else {
                al[u] = fma2(wv.x, rl[s], al[u]);
                ah[u] = fma2(wv.y, rh[s], ah[u]);
            }
        }
    }

#pragma unroll
    for (int u = 0; u < GRP; u++) {
        q4 o; o.x = al[u]; o.y = ah[u];
        oq[u * NQ] = o;                       // STG.128
    }
}

__global__ __launch_bounds__(THREADS, 6)      // cap <= 85 regs/thread
void fir_kernel(const float* __restrict__ x,
                const float* __restrict__ w,
                float* __restrict__ out) {
    // thread -> (b, tg, quad); lanes 0..7 share tg and step q, so the 8 lanes
    // of one tg cover a full 128B row; a warp covers 4 tgs (4 lines / access).
    const int g  = blockIdx.x * THREADS + threadIdx.x;
    const int q  = g & (NQ - 1);
    const int tg = (g >> 3) & (T_SZ / GRP - 1);   // 0..255
    const int b  = g >> 11;                       // 0..63
    const int t0 = tg * GRP;

    const long base = ((long)b * T_SZ + t0) * NQ + q;   // in q4 units
    const q4* xq = (const q4*)x + base;
    q4*       oq = (q4*)out + base;
    const q4* wq = (const q4*)w + q;

    if (t0 >= F_SZ)
        fir_item<false>(xq, oq, wq, t0);
    else
        fir_item<true>(xq, oq, wq, t0);       // tg 0 (t0=0) and tg 1 (t0=8)
}

extern "C" void kernel_launch(void* const* d_in, const int* in_sizes, int n_in,
                              void* d_out, int out_size) {
    const float* x = (const float*)d_in[0];   // [64, 2048, 32]
    const float* w = (const float*)d_in[1];   // [16, 32]
    float* out = (float*)d_out;

    const int total = B_SZ * (T_SZ / GRP) * NQ;          // 131072 threads
    fir_kernel<<<total / THREADS, THREADS>>>(x, w, out); // 1024 blocks
}

// round 16
// speedup vs baseline: 1.1522x; 1.1522x over previous
#include <cuda_runtime.h>

// FIR: out[b,t,c] = sum_{i=0..15} w[i,c] * x[b, t-15+i, c]   (causal, zero-padded)
// x: [B=64, T=2048, C=32] fp32, w: [16, 32] fp32, out: [B, T, C] fp32.
//
// Round 16: R9 (champion: streaming accs, GRP=8, fma2, 64-reg cap, no x-smem)
// with ONE change: taps staged in smem per block (2KB, 1 float4/thread + one
// 128-thread barrier) and read via 16 conflict-free LDS.64 instead of 16
// LDG.64. Global loads per thread drop 39 -> 23, cutting L1tex wavefront
// queueing -- the latency inflator indicated by R9's metrics.

#define B_SZ 64
#define T_SZ 2048
#define C_SZ 32
#define F_SZ 16
#define GRP  8
#define HALO (F_SZ - 1)          // 15
#define WIN  (GRP + HALO)        // 23
#define NPAIR (C_SZ / 2)         // 16
#define THREADS 128

typedef unsigned long long u64;

__device__ __forceinline__ u64 fma2(u64 a, u64 b, u64 c) {
    u64 d;
    asm("fma.rn.f32x2 %0, %1, %2, %3;" : "=l"(d) : "l"(a), "l"(b), "l"(c));
    return d;
}
__device__ __forceinline__ u64 mul2(u64 a, u64 b) {
    u64 d;
    asm("mul.rn.f32x2 %0, %1, %2;" : "=l"(d) : "l"(a), "l"(b));
    return d;
}

__global__ __launch_bounds__(THREADS, 8)   // cap 64 regs/thread
void fir_kernel(const float* __restrict__ x,
                const float* __restrict__ w,
                float* __restrict__ out) {
    __shared__ u64 wsm[F_SZ * NPAIR];             // 2KB: all taps, packed pairs

    const int tid = threadIdx.x;

    // stage taps: 128 threads x 1 float4 = 512 floats = whole w
    ((float4*)wsm)[tid] = ((const float4*)w)[tid];
    __syncthreads();

    // item id -> (b, time-group, channel-pair); lanes 0..15 share tg and step
    // cp, so each half-warp LDG.64 covers one 128B line.
    const int g  = blockIdx.x * THREADS + tid;
    const int cp = g & (NPAIR - 1);
    const int tg = (g >> 4) & (T_SZ / GRP - 1);   // 0..255
    const int b  = g >> 12;
    const int t0 = tg * GRP;

    const long base = ((long)b * T_SZ + t0) * NPAIR + cp;
    const u64* xp = (const u64*)x + base;

    // taps for this channel pair from smem (16 conflict-free LDS.64)
    u64 wp[F_SZ];
#pragma unroll
    for (int i = 0; i < F_SZ; i++) wp[i] = wsm[i * NPAIR + cp];

    u64 acc[GRP];

    if (t0 >= F_SZ) {
        // common path: full halo in-bounds, no predicates
#pragma unroll
        for (int j = 0; j < WIN; j++) {
            const u64 xv = xp[(j - HALO) * NPAIR];
            const int ulo = (j - HALO < 0) ? 0 : j - HALO;
            const int uhi = (j < GRP - 1) ? j : GRP - 1;
#pragma unroll
            for (int u = ulo; u <= uhi; u++)
                acc[u] = (j == u) ? mul2(wp[j - u], xv)
                                  : fma2(wp[j - u], xv, acc[u]);
        }
    } else {
        // t0 in {0, 8}: zero-pad halo (also blocks cross-batch reads)
#pragma unroll
        for (int j = 0; j < WIN; j++) {
            const int t = t0 - HALO + j;
            const u64 xv = (t >= 0) ? xp[(j - HALO) * NPAIR] : 0ULL;
            const int ulo = (j - HALO < 0) ? 0 : j - HALO;
            const int uhi = (j < GRP - 1) ? j : GRP - 1;
#pragma unroll
            for (int u = ulo; u <= uhi; u++)
                acc[u] = (j == u) ? mul2(wp[j - u], xv)
                                  : fma2(wp[j - u], xv, acc[u]);
        }
    }

    u64* op = (u64*)out + base;
#pragma unroll
    for (int u = 0; u < GRP; u++)
        op[u * NPAIR] = acc[u];
}

extern "C" void kernel_launch(void* const* d_in, const int* in_sizes, int n_in,
                              void* d_out, int out_size) {
    const float* x = (const float*)d_in[0];   // [64, 2048, 32]
    const float* w = (const float*)d_in[1];   // [16, 32]
    float* out = (float*)d_out;

    const int total = B_SZ * (T_SZ / GRP) * NPAIR;       // 262144 threads
    fir_kernel<<<total / THREADS, THREADS>>>(x, w, out); // 2048 blocks
}

// round 17
// speedup vs baseline: 1.1988x; 1.0404x over previous
#include <cuda_runtime.h>

// FIR: out[b,t,c] = sum_{i=0..15} w[i,c] * x[b, t-15+i, c]   (causal, zero-padded)
// x: [B=64, T=2048, C=32] fp32, w: [16, 32] fp32, out: [B, T, C] fp32.
//
// Round 17: split-tap + shfl combine. Warp = one (batch, 8-timestep group).
// Lane (cp, h): channel pair cp, tap half h (taps 8h..8h+7). Each thread
// streams only 15 window loads and holds 8 taps + 8 accs (~48 regs ->
// ~2x residency vs R9). Partials combined with shfl.bfly(16) + add2;
// h0 stores timesteps 0-3, h1 stores 4-7.

#define B_SZ 64
#define T_SZ 2048
#define C_SZ 32
#define F_SZ 16
#define GRP  8
#define HT   8                   // taps per half
#define NPAIR (C_SZ / 2)         // 16
#define THREADS 128
#define NTG (T_SZ / GRP)         // 256 time-groups per batch

typedef unsigned long long u64;

__device__ __forceinline__ u64 fma2(u64 a, u64 b, u64 c) {
    u64 d;
    asm("fma.rn.f32x2 %0, %1, %2, %3;" : "=l"(d) : "l"(a), "l"(b), "l"(c));
    return d;
}
__device__ __forceinline__ u64 mul2(u64 a, u64 b) {
    u64 d;
    asm("mul.rn.f32x2 %0, %1, %2;" : "=l"(d) : "l"(a), "l"(b));
    return d;
}
__device__ __forceinline__ u64 add2(u64 a, u64 b) {
    u64 d;
    asm("add.rn.f32x2 %0, %1, %2;" : "=l"(d) : "l"(a), "l"(b));
    return d;
}

__global__ __launch_bounds__(THREADS, 9)   // cap 56 regs/thread
void fir_kernel(const float* __restrict__ x,
                const float* __restrict__ w,
                float* __restrict__ out) {
    const int lane = threadIdx.x & 31;
    const int cp   = lane & (NPAIR - 1);   // channel pair 0..15
    const int h    = lane >> 4;            // tap half 0/1

    const int wg = (blockIdx.x * THREADS + threadIdx.x) >> 5;  // global warp id
    const int tg = wg & (NTG - 1);         // 0..255
    const int b  = wg >> 8;                // 0..63
    const int t0 = tg * GRP;

    // taps for this half: wp[k] = w[8h + k] (pair cp). L1-hot broadcast.
    const u64* wpr = (const u64*)w;        // [16][16] pairs
    u64 wp[HT];
#pragma unroll
    for (int k = 0; k < HT; k++) wp[k] = wpr[(HT * h + k) * NPAIR + cp];

    // window rows for this half: t = t0 + 8h - 15 + j, j = 0..14
    const int tbase = t0 + HT * h - (F_SZ - 1);
    const u64* xph = (const u64*)x
                   + ((long)b * T_SZ + tbase) * NPAIR + cp;

    // partial: acc[u] = sum_{k=0..7} w[8h+k] * x[t0+u-15+8h+k]
    // stream j: x row tbase+j feeds (k = j-u) for u in [j-7, j], first touch j==u.
    u64 acc[GRP];
    if (tg >= 2) {
        // tbase >= 1: all rows in-bounds, no predicates
#pragma unroll
        for (int j = 0; j < HT + GRP - 1; j++) {
            const u64 xv = xph[j * NPAIR];
            const int ulo = (j - (HT - 1) < 0) ? 0 : j - (HT - 1);
            const int uhi = (j < GRP - 1) ? j : GRP - 1;
#pragma unroll
            for (int u = ulo; u <= uhi; u++)
                acc[u] = (j == u) ? mul2(wp[j - u], xv)
                                  : fma2(wp[j - u], xv, acc[u]);
        }
    } else {
        // tg 0/1: rows with t < 0 are zero padding (also blocks cross-batch)
#pragma unroll
        for (int j = 0; j < HT + GRP - 1; j++) {
            const u64 xv = (tbase + j >= 0) ? xph[j * NPAIR] : 0ULL;
            const int ulo = (j - (HT - 1) < 0) ? 0 : j - (HT - 1);
            const int uhi = (j < GRP - 1) ? j : GRP - 1;
#pragma unroll
            for (int u = ulo; u <= uhi; u++)
                acc[u] = (j == u) ? mul2(wp[j - u], xv)
                                  : fma2(wp[j - u], xv, acc[u]);
        }
    }

    // combine halves: out[u] = p0[u] + p1[u]; h0 stores u 0-3, h1 stores u 4-7
    u64* op = (u64*)out + ((long)b * T_SZ + t0) * NPAIR + cp;
#pragma unroll
    for (int u = 0; u < GRP; u++) {
        const u64 other = __shfl_xor_sync(0xFFFFFFFFu, acc[u], 16);
        const u64 tot = add2(acc[u], other);
        if ((u >> 2) == h)
            op[u * NPAIR] = tot;
    }
}

extern "C" void kernel_launch(void* const* d_in, const int* in_sizes, int n_in,
                              void* d_out, int out_size) {
    const float* x = (const float*)d_in[0];   // [64, 2048, 32]
    const float* w = (const float*)d_in[1];   // [16, 32]
    float* out = (float*)d_out;

    const int total = B_SZ * NTG * 32;                   // 524288 threads
    fir_kernel<<<total / THREADS, THREADS>>>(x, w, out); // 4096 blocks
}